// round 16
// baseline (speedup 1.0000x reference)
#include <cuda_runtime.h>
#include <cuda_bf16.h>
#include <math.h>
#include <cstdint>
#include <stdint.h>

// ---------------- problem constants ----------------
#define B_    2
#define L_    2048
#define DIM_  2048
#define NH_   16
#define NKV_  4
#define HD_   128
#define FF_   8192
#define V_    32000
#define WIN_  1024
#define EPS_  1e-5f
#define NTOK  (B_*L_)          // 4096 rows

// bf16 plane offsets (elements): ow | per-layer {w13(interleaved), w2, wo}
#define OWB       0ull
#define LAYER_B   54525952ull
#define W13B(l)   (65536000ull + (size_t)(l) * LAYER_B)
#define W2B(l)    (W13B(l) + 33554432ull)
#define WOB(l)    (W2B(l) + 16777216ull)
#define WTOT      174587904ull

// ---------------- scratch (device globals; no allocation allowed) ----------------
__device__ float g_h   [(size_t)NTOK * DIM_];
__device__ float g_x   [(size_t)NTOK * DIM_];
__device__ float g_qkv [(size_t)NTOK * 3072];
__device__ float g_wqkv[2ull * DIM_ * 3072];
__device__ __nv_bfloat16 g_ahi[(size_t)NTOK * DIM_];   // rmsnorm/attn planes
__device__ __nv_bfloat16 g_alo[(size_t)NTOK * DIM_];
__device__ __nv_bfloat16 g_bhi[(size_t)NTOK * FF_];    // gate output planes
__device__ __nv_bfloat16 g_blo[(size_t)NTOK * FF_];
__device__ __nv_bfloat16 g_whi[WTOT];
__device__ __nv_bfloat16 g_wlo[WTOT];

// ================= shared helpers =================
__device__ __forceinline__ uint32_t smem_u32(const void* p) {
    uint32_t a;
    asm("{ .reg .u64 t; cvta.to.shared.u64 t, %1; cvt.u32.u64 %0, t; }" : "=r"(a) : "l"(p));
    return a;
}
__device__ __forceinline__ void bsplit(float v, __nv_bfloat16& h, __nv_bfloat16& l) {
    h = __float2bfloat16_rn(v);
    l = __float2bfloat16_rn(v - __bfloat162float(h));
}

// ======================================================================
// PART 1: exact-fp32 path (bit-identical math; verbatim where unchanged)
// ======================================================================

__global__ void embed_k(const int* __restrict__ ids, const float* __restrict__ tok,
                        float* __restrict__ h) {
    int row = blockIdx.x;
    int id  = ids[row];
    const float4* src = (const float4*)(tok + (size_t)id  * DIM_);
    float4*       dst = (float4*)      (h   + (size_t)row * DIM_);
    for (int t = threadIdx.x; t < DIM_ / 4; t += blockDim.x) dst[t] = src[t];
}

__global__ __launch_bounds__(256) void rmsnorm_k(const float* __restrict__ x,
                                                 const float* __restrict__ w,
                                                 float* __restrict__ y) {
    int row = blockIdx.x;
    int t   = threadIdx.x;
    const float4* xr = (const float4*)(x + (size_t)row * DIM_);
    float4 a = xr[t], b = xr[t + 256];
    float ss = a.x*a.x + a.y*a.y + a.z*a.z + a.w*a.w
             + b.x*b.x + b.y*b.y + b.z*b.z + b.w*b.w;
#pragma unroll
    for (int o = 16; o; o >>= 1) ss += __shfl_xor_sync(0xffffffffu, ss, o);
    __shared__ float red[8];
    if ((t & 31) == 0) red[t >> 5] = ss;
    __syncthreads();
    float tot = red[0]+red[1]+red[2]+red[3]+red[4]+red[5]+red[6]+red[7];
    float r = rsqrtf(tot * (1.0f / (float)DIM_) + EPS_);
    const float4* wr = (const float4*)w;
    float4 wa = wr[t], wb = wr[t + 256];
    float4* yr = (float4*)(y + (size_t)row * DIM_);
    yr[t]       = make_float4(a.x*r*wa.x, a.y*r*wa.y, a.z*r*wa.z, a.w*r*wa.w);
    yr[t + 256] = make_float4(b.x*r*wb.x, b.y*r*wb.y, b.z*r*wb.z, b.w*r*wb.w);
}

__global__ __launch_bounds__(256) void rmsnorm_cvt_k(const float* __restrict__ x,
                                                     const float* __restrict__ w,
                                                     __nv_bfloat16* __restrict__ yhi,
                                                     __nv_bfloat16* __restrict__ ylo) {
    int row = blockIdx.x;
    int t   = threadIdx.x;
    const float4* xr = (const float4*)(x + (size_t)row * DIM_);
    float4 a = xr[t], b = xr[t + 256];
    float ss = a.x*a.x + a.y*a.y + a.z*a.z + a.w*a.w
             + b.x*b.x + b.y*b.y + b.z*b.z + b.w*b.w;
#pragma unroll
    for (int o = 16; o; o >>= 1) ss += __shfl_xor_sync(0xffffffffu, ss, o);
    __shared__ float red[8];
    if ((t & 31) == 0) red[t >> 5] = ss;
    __syncthreads();
    float tot = red[0]+red[1]+red[2]+red[3]+red[4]+red[5]+red[6]+red[7];
    float r = rsqrtf(tot * (1.0f / (float)DIM_) + EPS_);
    const float4* wr = (const float4*)w;
    float4 wa = wr[t], wb = wr[t + 256];
    float va[4] = {a.x*r*wa.x, a.y*r*wa.y, a.z*r*wa.z, a.w*r*wa.w};
    float vb[4] = {b.x*r*wb.x, b.y*r*wb.y, b.z*r*wb.z, b.w*r*wb.w};
    __nv_bfloat16 h0, h1, h2, h3, l0, l1, l2, l3;
    size_t base = (size_t)row * DIM_;
    bsplit(va[0], h0, l0); bsplit(va[1], h1, l1);
    bsplit(va[2], h2, l2); bsplit(va[3], h3, l3);
    ((__nv_bfloat162*)(yhi + base + t*4))[0] = __halves2bfloat162(h0, h1);
    ((__nv_bfloat162*)(yhi + base + t*4))[1] = __halves2bfloat162(h2, h3);
    ((__nv_bfloat162*)(ylo + base + t*4))[0] = __halves2bfloat162(l0, l1);
    ((__nv_bfloat162*)(ylo + base + t*4))[1] = __halves2bfloat162(l2, l3);
    bsplit(vb[0], h0, l0); bsplit(vb[1], h1, l1);
    bsplit(vb[2], h2, l2); bsplit(vb[3], h3, l3);
    ((__nv_bfloat162*)(yhi + base + (t+256)*4))[0] = __halves2bfloat162(h0, h1);
    ((__nv_bfloat162*)(yhi + base + (t+256)*4))[1] = __halves2bfloat162(h2, h3);
    ((__nv_bfloat162*)(ylo + base + (t+256)*4))[0] = __halves2bfloat162(l0, l1);
    ((__nv_bfloat162*)(ylo + base + (t+256)*4))[1] = __halves2bfloat162(l2, l3);
}

__global__ void qkv_concat_k(const float* __restrict__ wq, const float* __restrict__ wk,
                             const float* __restrict__ wv, float* __restrict__ out) {
    size_t idx = (size_t)blockIdx.x * blockDim.x + threadIdx.x;
    size_t n4 = idx % 768, kk = idx / 768;
    size_t n = n4 * 4;
    float4 v;
    if (n < 2048)      v = *(const float4*)(wq + kk * 2048 + n);
    else if (n < 2560) v = *(const float4*)(wk + kk * 512 + (n - 2048));
    else               v = *(const float4*)(wv + kk * 512 + (n - 2560));
    ((float4*)out)[idx] = v;
}

__global__ void rope_pk(float* __restrict__ base, int nheads, int col_off) {
    int idx = blockIdx.x * blockDim.x + threadIdx.x;
    int i    = idx & 63;
    int rest = idx >> 6;
    int h    = rest % nheads;
    int row  = rest / nheads;
    int l    = row & (L_ - 1);
    double e   = -(double)(2 * i) * (1.0 / (double)HD_) * 9.210340371976184;
    double ang = (double)l * exp(e);
    double sd, cd;
    sincos(ang, &sd, &cd);
    float c = (float)cd, s = (float)sd;
    float2* p = (float2*)(base + (size_t)row * 3072 + col_off + h * HD_) + i;
    float2 xv = *p;
    *p = make_float2(xv.x * c - xv.y * s, xv.x * s + xv.y * c);
}

// smem-tiled sliding-window GQA attention — single-MUFU online softmax.
// exp identity: nm = max(m,sc) makes one of exp(m-nm), exp(sc-nm) exactly 1.0;
// emax = __expf(-|sc-m|) is the other, routed by SEL. Bit-identical to the
// two-expf form (fl(m-sc) == -fl(sc-m); update expressions unchanged).
#define CK 64
#define ASMEM (2 * CK * HD_ * 4)

__global__ __launch_bounds__(1024)
void attn_tile_k(const float* __restrict__ qkv,
                 __nv_bfloat16* __restrict__ ohi, __nv_bfloat16* __restrict__ olo) {
    extern __shared__ float sbuf[];
    float* sk = sbuf;
    float* sv = sbuf + CK * HD_;

    const int w    = threadIdx.x >> 5;
    const int lane = threadIdx.x & 31;
    const int q0   = blockIdx.x * 8;
    const int kvh  = blockIdx.y;
    const int b    = blockIdx.z;
    const int qpos = q0 + (w >> 2);
    const int h    = kvh * 4 + (w & 3);

    const float4* qp = (const float4*)(qkv + (size_t)(b * L_ + qpos) * 3072 + h * HD_);
    const float4  qv = qp[lane];

    int start = qpos - (WIN_ - 1); if (start < 0) start = 0;
    int start0 = q0 - (WIN_ - 1);  if (start0 < 0) start0 = 0;
    const int base0 = start0 & ~(CK - 1);
    const int qend  = q0 + 7;
    const float SCALE = 11.313708498984761f;

    float m = -1e30f, ssum = 0.f;
    float4 acc = make_float4(0.f, 0.f, 0.f, 0.f);

    for (int base = base0; base <= qend; base += CK) {
        __syncthreads();
        for (int i = threadIdx.x; i < CK * 32; i += 1024) {
            int row = i >> 5, c4 = i & 31;
            size_t g = ((size_t)(b * L_ + base + row)) * 3072 + 2048 + kvh * HD_ + c4 * 4;
            ((float4*)sk)[i] = *(const float4*)(qkv + g);
            ((float4*)sv)[i] = *(const float4*)(qkv + g + 512);
        }
        __syncthreads();

        int lo = start > base ? start : base;
        int hi = qpos < base + CK - 1 ? qpos : base + CK - 1;
        for (int kp = lo; kp <= hi; ++kp) {
            float4 kv4 = ((const float4*)sk)[(kp - base) * 32 + lane];
            float d = qv.x*kv4.x + qv.y*kv4.y + qv.z*kv4.z + qv.w*kv4.w;
            d += __shfl_xor_sync(0xffffffffu, d, 16);
            d += __shfl_xor_sync(0xffffffffu, d, 8);
            d += __shfl_xor_sync(0xffffffffu, d, 4);
            d += __shfl_xor_sync(0xffffffffu, d, 2);
            d += __shfl_xor_sync(0xffffffffu, d, 1);
            float sc   = d * SCALE;
            float nm   = fmaxf(m, sc);
            float emax = __expf(-fabsf(sc - m));
            bool  up   = sc > m;
            float corr = up ? emax : 1.0f;
            float p    = up ? 1.0f : emax;
            float4 vv  = ((const float4*)sv)[(kp - base) * 32 + lane];
            ssum  = ssum * corr + p;
            acc.x = acc.x * corr + p * vv.x;
            acc.y = acc.y * corr + p * vv.y;
            acc.z = acc.z * corr + p * vv.z;
            acc.w = acc.w * corr + p * vv.w;
            m = nm;
        }
    }

    float inv = 1.f / ssum;
    float o0 = acc.x * inv, o1 = acc.y * inv, o2 = acc.z * inv, o3 = acc.w * inv;
    __nv_bfloat16 h0, h1, h2, h3, l0, l1, l2, l3;
    bsplit(o0, h0, l0); bsplit(o1, h1, l1); bsplit(o2, h2, l2); bsplit(o3, h3, l3);
    size_t obase = ((size_t)(b * L_ + qpos) * NH_ + h) * HD_ + lane * 4;
    ((__nv_bfloat162*)(ohi + obase))[0] = __halves2bfloat162(h0, h1);
    ((__nv_bfloat162*)(ohi + obase))[1] = __halves2bfloat162(h2, h3);
    ((__nv_bfloat162*)(olo + obase))[0] = __halves2bfloat162(l0, l1);
    ((__nv_bfloat162*)(olo + obase))[1] = __halves2bfloat162(l2, l3);
}

// ---------------- f32x2 packed-FMA SGEMM (verbatim) ----------------
#define BM 128
#define BN 128
#define BK 8

__device__ __forceinline__ uint64_t packdup(float x) {
    uint64_t u;
    uint32_t b = __float_as_uint(x);
    asm("mov.b64 %0, {%1, %2};" : "=l"(u) : "r"(b), "r"(b));
    return u;
}
__device__ __forceinline__ void unpack2(uint64_t u, float& lo, float& hi) {
    uint32_t a, b;
    asm("mov.b64 {%0, %1}, %2;" : "=r"(a), "=r"(b) : "l"(u));
    lo = __uint_as_float(a);
    hi = __uint_as_float(b);
}

__global__ __launch_bounds__(256, 2)
void sgemm_k(const float* __restrict__ A, const float* __restrict__ B,
             float* __restrict__ C, int M, int N, int K) {
    __shared__ float As[2][BK][BM];
    __shared__ float Bs[2][BK][BN];

    const int tid = threadIdx.x;
    const int tc  = tid & 15;
    const int tr  = tid >> 4;

    const int num_m = M >> 7, num_n = N >> 7;
    int pid   = blockIdx.x;
    int width = 8 * num_n;
    int gid   = pid / width;
    int rem   = num_m - gid * 8;
    int gsz   = rem < 8 ? rem : 8;
    int pm    = gid * 8 + (pid % gsz);
    int pn    = (pid % width) / gsz;
    const int row0 = pm << 7, col0 = pn << 7;

    const int a_r = tid >> 1;
    const int a_c = (tid & 1) << 2;
    const int b_r = tid >> 5;
    const int b_c = (tid & 31) << 2;

    const float* Ap = A + (size_t)(row0 + a_r) * K + a_c;
    const float* Bp = B + (size_t)b_r * N + col0 + b_c;

    uint64_t acc2[4][8];
#pragma unroll
    for (int i = 0; i < 4; ++i)
#pragma unroll
        for (int j = 0; j < 8; ++j) acc2[i][j] = 0ull;

    float4 av = *(const float4*)Ap;  Ap += BK;
    float4 bv = *(const float4*)Bp;  Bp += (size_t)BK * N;
    As[0][a_c + 0][a_r] = av.x;
    As[0][a_c + 1][a_r] = av.y;
    As[0][a_c + 2][a_r] = av.z;
    As[0][a_c + 3][a_r] = av.w;
    *(float4*)&Bs[0][b_r][b_c] = bv;
    __syncthreads();

    const int CH = K / BK;
    for (int c = 0; c < CH; ++c) {
        const int buf = c & 1;
        if (c + 1 < CH) {
            av = *(const float4*)Ap;  Ap += BK;
            bv = *(const float4*)Bp;  Bp += (size_t)BK * N;
        }
#pragma unroll
        for (int kk = 0; kk < BK; ++kk) {
            const uint64_t* ap2 = (const uint64_t*)&As[buf][kk][tr * 8];
            uint64_t a2_0 = ap2[0], a2_1 = ap2[1], a2_2 = ap2[2], a2_3 = ap2[3];
            float br[8];
            *(float4*)&br[0] = *(const float4*)&Bs[buf][kk][tc * 8];
            *(float4*)&br[4] = *(const float4*)&Bs[buf][kk][tc * 8 + 4];
#pragma unroll
            for (int j = 0; j < 8; ++j) {
                uint64_t b2 = packdup(br[j]);
                asm("fma.rn.f32x2 %0, %1, %2, %0;" : "+l"(acc2[0][j]) : "l"(a2_0), "l"(b2));
                asm("fma.rn.f32x2 %0, %1, %2, %0;" : "+l"(acc2[1][j]) : "l"(a2_1), "l"(b2));
                asm("fma.rn.f32x2 %0, %1, %2, %0;" : "+l"(acc2[2][j]) : "l"(a2_2), "l"(b2));
                asm("fma.rn.f32x2 %0, %1, %2, %0;" : "+l"(acc2[3][j]) : "l"(a2_3), "l"(b2));
            }
        }
        if (c + 1 < CH) {
            const int nb = buf ^ 1;
            As[nb][a_c + 0][a_r] = av.x;
            As[nb][a_c + 1][a_r] = av.y;
            As[nb][a_c + 2][a_r] = av.z;
            As[nb][a_c + 3][a_r] = av.w;
            *(float4*)&Bs[nb][b_r][b_c] = bv;
        }
        __syncthreads();
    }

#pragma unroll
    for (int i2 = 0; i2 < 4; ++i2) {
        float lo[8], hi[8];
#pragma unroll
        for (int j = 0; j < 8; ++j) unpack2(acc2[i2][j], lo[j], hi[j]);

        size_t r_lo = (size_t)(row0 + tr * 8 + 2 * i2);
        size_t r_hi = r_lo + 1;
        float* cp_lo = C + r_lo * N + col0 + tc * 8;
        float* cp_hi = C + r_hi * N + col0 + tc * 8;
        ((float4*)cp_lo)[0] = make_float4(lo[0], lo[1], lo[2], lo[3]);
        ((float4*)cp_lo)[1] = make_float4(lo[4], lo[5], lo[6], lo[7]);
        ((float4*)cp_hi)[0] = make_float4(hi[0], hi[1], hi[2], hi[3]);
        ((float4*)cp_hi)[1] = make_float4(hi[4], hi[5], hi[6], hi[7]);
    }
}

static inline void sgemm(const float* A, const float* B, float* C, int M, int N, int K) {
    int tiles = (M / BM) * (N / BN);
    sgemm_k<<<tiles, 256>>>(A, B, C, M, N, K);
}

// ======================================================================
// PART 2: bf16 hi/lo 3-term mma GEMM — 64x64 warp tiles (round 15 core)
// EPI: 0 = store fp32; 1 = +residual; 2 = silu-gate on (even,odd) column
// pairs -> bf16 hi/lo planes (requires interleaved w1/w3 weight layout).
// ======================================================================

__device__ __forceinline__ void cp16(uint32_t s, const void* g) {
    asm volatile("cp.async.cg.shared.global [%0], [%1], 16;" :: "r"(s), "l"(g));
}
__device__ __forceinline__ void ldsm4(uint32_t* r, uint32_t addr) {
    asm volatile("ldmatrix.sync.aligned.m8n8.x4.shared.b16 {%0,%1,%2,%3}, [%4];"
                 : "=r"(r[0]), "=r"(r[1]), "=r"(r[2]), "=r"(r[3]) : "r"(addr));
}
#define MMA16816(d, a, b) \
    asm volatile("mma.sync.aligned.m16n8k16.row.col.f32.bf16.bf16.f32 " \
        "{%0,%1,%2,%3}, {%4,%5,%6,%7}, {%8,%9}, {%0,%1,%2,%3};" \
        : "+f"((d)[0]), "+f"((d)[1]), "+f"((d)[2]), "+f"((d)[3]) \
        : "r"((a)[0]), "r"((a)[1]), "r"((a)[2]), "r"((a)[3]), "r"((b)[0]), "r"((b)[1]))

__device__ __forceinline__ uint32_t swz(int row, int ck) {
    return (uint32_t)((row * 4 + (ck ^ ((row >> 1) & 3))) * 16);
}

#define MSTG_BYTES 32768
#define MGSMEM (3 * MSTG_BYTES)

__global__ __launch_bounds__(128, 2)
void mma_gemm_k(const __nv_bfloat16* __restrict__ Ahi, const __nv_bfloat16* __restrict__ Alo,
                const __nv_bfloat16* __restrict__ Bhi, const __nv_bfloat16* __restrict__ Blo,
                const float* __restrict__ R, float* __restrict__ C,
                __nv_bfloat16* __restrict__ Ghi, __nv_bfloat16* __restrict__ Glo,
                int M, int N, int K, int EPI) {
    extern __shared__ __align__(128) char smem[];
    const uint32_t sb = smem_u32(smem);
    const int tid = threadIdx.x, wid = tid >> 5, lane = tid & 31;

    const int num_n = N >> 7;
    int pid = blockIdx.x;
    const int GM = 8;
    int width = GM * num_n;
    int gid = pid / width;
    int rem = (M >> 7) - gid * GM;
    int gsz = rem < GM ? rem : GM;
    int pm = gid * GM + (pid % gsz);
    int pn = (pid % width) / gsz;
    const int m0 = pm << 7, n0 = pn << 7;

    const size_t Kb = (size_t)K * 2;
    const int CH = K >> 5;

    const int wm = (wid >> 1) * 64;   // 2x2 warp grid, warp tile 64x64
    const int wn = (wid & 1) * 64;

    float acc[4][8][4];
#pragma unroll
    for (int i = 0; i < 4; ++i)
#pragma unroll
        for (int j = 0; j < 8; ++j)
#pragma unroll
            for (int r = 0; r < 4; ++r) acc[i][j][r] = 0.f;

    auto load = [&](int s, int chunk) {
        uint32_t st = sb + (uint32_t)s * (uint32_t)MSTG_BYTES;
        size_t kb0 = (size_t)chunk * 64;
#pragma unroll
        for (int part = 0; part < 4; ++part) {
            int q = part * 128 + tid;
            int r = q >> 2, ck = q & 3;
            uint32_t so = swz(r, ck);
            size_t ga = (size_t)(m0 + r) * Kb + kb0 + (size_t)ck * 16;
            size_t gb = (size_t)(n0 + r) * Kb + kb0 + (size_t)ck * 16;
            cp16(st +          so, (const char*)Ahi + ga);
            cp16(st +  8192u + so, (const char*)Alo + ga);
            cp16(st + 16384u + so, (const char*)Bhi + gb);
            cp16(st + 24576u + so, (const char*)Blo + gb);
        }
    };

    load(0, 0);
    asm volatile("cp.async.commit_group;" ::: "memory");
    load(1, 1);
    asm volatile("cp.async.commit_group;" ::: "memory");

    const int a_row = wm + (lane & 7) + ((lane >> 3) & 1) * 8;
    const int a_ckl = (lane >> 4) & 1;
    const int b_row = wn + (lane & 7) + ((lane >> 4) & 1) * 8;
    const int b_ckl = (lane >> 3) & 1;

    for (int c = 0; c < CH; ++c) {
        const int s = c % 3;
        if (c + 1 < CH) asm volatile("cp.async.wait_group 1;" ::: "memory");
        else            asm volatile("cp.async.wait_group 0;" ::: "memory");
        __syncthreads();
        if (c + 2 < CH) {
            load((c + 2) % 3, c + 2);
            asm volatile("cp.async.commit_group;" ::: "memory");
        }
        const uint32_t stA  = sb + (uint32_t)s * (uint32_t)MSTG_BYTES;
        const uint32_t stAl = stA + 8192u;
        const uint32_t stB  = stA + 16384u;
        const uint32_t stBl = stA + 24576u;
#pragma unroll
        for (int ks = 0; ks < 2; ++ks) {
            const int cka = ks * 2 + a_ckl;
            const int ckb = ks * 2 + b_ckl;
            uint32_t Ah[4][4], Al[4][4];
#pragma unroll
            for (int mi = 0; mi < 4; ++mi) {
                uint32_t so = swz(a_row + mi * 16, cka);
                ldsm4(Ah[mi], stA  + so);
                ldsm4(Al[mi], stAl + so);
            }
#pragma unroll
            for (int nq = 0; nq < 4; ++nq) {
                uint32_t Bh[4], Bl[4];
                uint32_t so = swz(b_row + nq * 16, ckb);
                ldsm4(Bh, stB  + so);
                ldsm4(Bl, stBl + so);
#pragma unroll
                for (int mi = 0; mi < 4; ++mi)
#pragma unroll
                    for (int jj = 0; jj < 2; ++jj) {
                        const int nj = nq * 2 + jj;
                        MMA16816(acc[mi][nj], Ah[mi], &Bh[jj * 2]);
                        MMA16816(acc[mi][nj], Al[mi], &Bh[jj * 2]);
                        MMA16816(acc[mi][nj], Ah[mi], &Bl[jj * 2]);
                    }
            }
        }
    }

#pragma unroll
    for (int mi = 0; mi < 4; ++mi) {
        int r0 = m0 + wm + mi * 16 + (lane >> 2);
#pragma unroll
        for (int nj = 0; nj < 8; ++nj) {
            int c0 = n0 + wn + nj * 8 + (lane & 3) * 2;
            if (EPI == 2) {
                // silu-gate: columns (c0, c0+1) = (w1_j, w3_j), j = c0/2
                int j0 = c0 >> 1;
                float gA = acc[mi][nj][0] / (1.f + __expf(-acc[mi][nj][0])) * acc[mi][nj][1];
                float gB = acc[mi][nj][2] / (1.f + __expf(-acc[mi][nj][2])) * acc[mi][nj][3];
                __nv_bfloat16 hh, ll;
                bsplit(gA, hh, ll);
                Ghi[(size_t)r0 * FF_ + j0] = hh;
                Glo[(size_t)r0 * FF_ + j0] = ll;
                bsplit(gB, hh, ll);
                Ghi[(size_t)(r0 + 8) * FF_ + j0] = hh;
                Glo[(size_t)(r0 + 8) * FF_ + j0] = ll;
            } else {
                float2 v0 = make_float2(acc[mi][nj][0], acc[mi][nj][1]);
                float2 v1 = make_float2(acc[mi][nj][2], acc[mi][nj][3]);
                if (EPI == 1) {
                    float2 q0 = *(const float2*)(R + (size_t)r0 * N + c0);
                    float2 q1 = *(const float2*)(R + (size_t)(r0 + 8) * N + c0);
                    v0.x += q0.x; v0.y += q0.y;
                    v1.x += q1.x; v1.y += q1.y;
                }
                *(float2*)(C + (size_t)r0 * N + c0)       = v0;
                *(float2*)(C + (size_t)(r0 + 8) * N + c0) = v1;
            }
        }
    }
}

// weight transpose + bf16 hi/lo split; cstride/coff support column interleave
__global__ __launch_bounds__(256) void cvt_wT_k(const float* __restrict__ W,
        __nv_bfloat16* __restrict__ hiT, __nv_bfloat16* __restrict__ loT,
        int K, int N, int cstride, int coff) {
    __shared__ float t[32][33];
    int tx = threadIdx.x, ty = threadIdx.y;
    int nb = blockIdx.x * 32, kb = blockIdx.y * 32;
#pragma unroll
    for (int r = 0; r < 4; ++r)
        t[ty + 8 * r][tx] = W[(size_t)(kb + ty + 8 * r) * N + nb + tx];
    __syncthreads();
#pragma unroll
    for (int r = 0; r < 4; ++r) {
        float v = t[tx][ty + 8 * r];
        __nv_bfloat16 h = __float2bfloat16_rn(v);
        __nv_bfloat16 l = __float2bfloat16_rn(v - __bfloat162float(h));
        size_t o = ((size_t)(nb + ty + 8 * r) * cstride + coff) * K + kb + tx;
        hiT[o] = h; loT[o] = l;
    }
}

static void bmma(const __nv_bfloat16* ahi, const __nv_bfloat16* alo,
                 const __nv_bfloat16* bhi, const __nv_bfloat16* blo,
                 const float* R, float* C,
                 __nv_bfloat16* ghi, __nv_bfloat16* glo,
                 int M, int N, int K, int epi) {
    int tiles = (M / 128) * (N / 128);
    mma_gemm_k<<<tiles, 128, MGSMEM>>>(ahi, alo, bhi, blo, R, C, ghi, glo, M, N, K, epi);
}

static void cvt_w(const float* W, __nv_bfloat16* hiT, __nv_bfloat16* loT,
                  int K, int N, int cstride, int coff) {
    dim3 g(N / 32, K / 32), b(32, 8);
    cvt_wT_k<<<g, b>>>(W, hiT, loT, K, N, cstride, coff);
}

// ================= launch =================
extern "C" void kernel_launch(void* const* d_in, const int* in_sizes, int n_in,
                              void* d_out, int out_size) {
    const int*   ids = (const int*)  d_in[0];
    const float* tok = (const float*)d_in[1];
    const float* anw = (const float*)d_in[2];
    const float* wq  = (const float*)d_in[3];
    const float* wk  = (const float*)d_in[4];
    const float* wv  = (const float*)d_in[5];
    const float* wo  = (const float*)d_in[6];
    const float* fnw = (const float*)d_in[7];
    const float* w1  = (const float*)d_in[8];
    const float* w2  = (const float*)d_in[9];
    const float* w3  = (const float*)d_in[10];
    const float* nw  = (const float*)d_in[11];
    const float* ow  = (const float*)d_in[12];
    float* out = (float*)d_out;

    cudaFuncSetAttribute(mma_gemm_k,  cudaFuncAttributeMaxDynamicSharedMemorySize, MGSMEM);
    cudaFuncSetAttribute(attn_tile_k, cudaFuncAttributeMaxDynamicSharedMemorySize, ASMEM);

    float *h, *x, *qkv, *wqkv;
    __nv_bfloat16 *ahi, *alo, *bhi, *blo, *whi, *wlo;
    cudaGetSymbolAddress((void**)&h,    g_h);
    cudaGetSymbolAddress((void**)&x,    g_x);
    cudaGetSymbolAddress((void**)&qkv,  g_qkv);
    cudaGetSymbolAddress((void**)&wqkv, g_wqkv);
    cudaGetSymbolAddress((void**)&ahi,  g_ahi);
    cudaGetSymbolAddress((void**)&alo,  g_alo);
    cudaGetSymbolAddress((void**)&bhi,  g_bhi);
    cudaGetSymbolAddress((void**)&blo,  g_blo);
    cudaGetSymbolAddress((void**)&whi,  g_whi);
    cudaGetSymbolAddress((void**)&wlo,  g_wlo);

    // bf16 planes: logits + per-layer {W13 interleaved, W2, WO}
    cvt_w(ow, whi + OWB, wlo + OWB, DIM_, V_, 1, 0);
    for (int l = 0; l < 2; ++l) {
        cvt_w(w1 + (size_t)l*DIM_*FF_,     whi + W13B(l), wlo + W13B(l), DIM_, FF_, 2, 0);
        cvt_w(w3 + (size_t)l*DIM_*FF_,     whi + W13B(l), wlo + W13B(l), DIM_, FF_, 2, 1);
        cvt_w(w2 + (size_t)l*FF_*DIM_,     whi + W2B(l),  wlo + W2B(l),  FF_, DIM_, 1, 0);
        cvt_w(wo + (size_t)l*2048ull*DIM_, whi + WOB(l),  wlo + WOB(l),  2048, DIM_, 1, 0);
    }

    // fp32 QKV concat per layer
    for (int l = 0; l < 2; ++l)
        qkv_concat_k<<<(DIM_ * 768) / 256, 256>>>(
            wq + (size_t)l * DIM_ * 2048, wk + (size_t)l * DIM_ * 512,
            wv + (size_t)l * DIM_ * 512,  wqkv + (size_t)l * DIM_ * 3072);

    embed_k<<<NTOK, 256>>>(ids, tok, h);

    for (int l = 0; l < 2; ++l) {
        // QKV + attention: exact fp32 path (both layers)
        rmsnorm_k<<<NTOK, 256>>>(h, anw + (size_t)l * DIM_, x);
        sgemm(x, wqkv + (size_t)l * DIM_ * 3072, qkv, NTOK, 3072, DIM_);
        rope_pk<<<(NTOK * NH_  * 64) / 256, 256>>>(qkv, NH_, 0);
        rope_pk<<<(NTOK * NKV_ * 64) / 256, 256>>>(qkv, NKV_, 2048);

        dim3 ag(L_ / 8, NKV_, B_);
        attn_tile_k<<<ag, 1024, ASMEM>>>(qkv, ahi, alo);

        // WO: bf16 mma (+residual into h)
        bmma(ahi, alo, whi + WOB(l), wlo + WOB(l), h, h, nullptr, nullptr,
             NTOK, DIM_, 2048, 1);

        // FFN: rmsnorm->planes, W13 with fused silu-gate epilogue -> gate planes
        rmsnorm_cvt_k<<<NTOK, 256>>>(h, fnw + (size_t)l * DIM_, ahi, alo);
        bmma(ahi, alo, whi + W13B(l), wlo + W13B(l), nullptr, nullptr, bhi, blo,
             NTOK, 16384, DIM_, 2);

        // W2 (+residual into h)
        bmma(bhi, blo, whi + W2B(l), wlo + W2B(l), h, h, nullptr, nullptr,
             NTOK, DIM_, FF_, 1);
    }

    rmsnorm_cvt_k<<<NTOK, 256>>>(h, nw, ahi, alo);
    bmma(ahi, alo, whi + OWB, wlo + OWB, nullptr, out, nullptr, nullptr,
         NTOK, V_, DIM_, 0);
}

// round 17
// speedup vs baseline: 1.0102x; 1.0102x over previous
#include <cuda_runtime.h>
#include <cuda_bf16.h>
#include <math.h>
#include <cstdint>
#include <stdint.h>

// ---------------- problem constants ----------------
#define B_    2
#define L_    2048
#define DIM_  2048
#define NH_   16
#define NKV_  4
#define HD_   128
#define FF_   8192
#define V_    32000
#define WIN_  1024
#define EPS_  1e-5f
#define NTOK  (B_*L_)          // 4096 rows

// bf16 plane offsets (elements): ow | per-layer {w13(interleaved), w2, wo}
#define OWB       0ull
#define LAYER_B   54525952ull
#define W13B(l)   (65536000ull + (size_t)(l) * LAYER_B)
#define W2B(l)    (W13B(l) + 33554432ull)
#define WOB(l)    (W2B(l) + 16777216ull)
#define WTOT      174587904ull

// ---------------- scratch (device globals; no allocation allowed) ----------------
__device__ float g_h   [(size_t)NTOK * DIM_];
__device__ float g_x   [(size_t)NTOK * DIM_];
__device__ float g_qkv [(size_t)NTOK * 3072];
__device__ float g_wqkv[2ull * DIM_ * 3072];
__device__ __nv_bfloat16 g_ahi[(size_t)NTOK * DIM_];
__device__ __nv_bfloat16 g_alo[(size_t)NTOK * DIM_];
__device__ __nv_bfloat16 g_bhi[(size_t)NTOK * FF_];
__device__ __nv_bfloat16 g_blo[(size_t)NTOK * FF_];
__device__ __nv_bfloat16 g_whi[WTOT];
__device__ __nv_bfloat16 g_wlo[WTOT];

// ================= shared helpers =================
__device__ __forceinline__ uint32_t smem_u32(const void* p) {
    uint32_t a;
    asm("{ .reg .u64 t; cvta.to.shared.u64 t, %1; cvt.u32.u64 %0, t; }" : "=r"(a) : "l"(p));
    return a;
}
__device__ __forceinline__ void bsplit(float v, __nv_bfloat16& h, __nv_bfloat16& l) {
    h = __float2bfloat16_rn(v);
    l = __float2bfloat16_rn(v - __bfloat162float(h));
}

// ======================================================================
// PART 1: exact-fp32 path (bit-identical math; verbatim where unchanged)
// ======================================================================

__global__ void embed_k(const int* __restrict__ ids, const float* __restrict__ tok,
                        float* __restrict__ h) {
    int row = blockIdx.x;
    int id  = ids[row];
    const float4* src = (const float4*)(tok + (size_t)id  * DIM_);
    float4*       dst = (float4*)      (h   + (size_t)row * DIM_);
    for (int t = threadIdx.x; t < DIM_ / 4; t += blockDim.x) dst[t] = src[t];
}

__global__ __launch_bounds__(256) void rmsnorm_k(const float* __restrict__ x,
                                                 const float* __restrict__ w,
                                                 float* __restrict__ y) {
    int row = blockIdx.x;
    int t   = threadIdx.x;
    const float4* xr = (const float4*)(x + (size_t)row * DIM_);
    float4 a = xr[t], b = xr[t + 256];
    float ss = a.x*a.x + a.y*a.y + a.z*a.z + a.w*a.w
             + b.x*b.x + b.y*b.y + b.z*b.z + b.w*b.w;
#pragma unroll
    for (int o = 16; o; o >>= 1) ss += __shfl_xor_sync(0xffffffffu, ss, o);
    __shared__ float red[8];
    if ((t & 31) == 0) red[t >> 5] = ss;
    __syncthreads();
    float tot = red[0]+red[1]+red[2]+red[3]+red[4]+red[5]+red[6]+red[7];
    float r = rsqrtf(tot * (1.0f / (float)DIM_) + EPS_);
    const float4* wr = (const float4*)w;
    float4 wa = wr[t], wb = wr[t + 256];
    float4* yr = (float4*)(y + (size_t)row * DIM_);
    yr[t]       = make_float4(a.x*r*wa.x, a.y*r*wa.y, a.z*r*wa.z, a.w*r*wa.w);
    yr[t + 256] = make_float4(b.x*r*wb.x, b.y*r*wb.y, b.z*r*wb.z, b.w*r*wb.w);
}

__global__ __launch_bounds__(256) void rmsnorm_cvt_k(const float* __restrict__ x,
                                                     const float* __restrict__ w,
                                                     __nv_bfloat16* __restrict__ yhi,
                                                     __nv_bfloat16* __restrict__ ylo) {
    int row = blockIdx.x;
    int t   = threadIdx.x;
    const float4* xr = (const float4*)(x + (size_t)row * DIM_);
    float4 a = xr[t], b = xr[t + 256];
    float ss = a.x*a.x + a.y*a.y + a.z*a.z + a.w*a.w
             + b.x*b.x + b.y*b.y + b.z*b.z + b.w*b.w;
#pragma unroll
    for (int o = 16; o; o >>= 1) ss += __shfl_xor_sync(0xffffffffu, ss, o);
    __shared__ float red[8];
    if ((t & 31) == 0) red[t >> 5] = ss;
    __syncthreads();
    float tot = red[0]+red[1]+red[2]+red[3]+red[4]+red[5]+red[6]+red[7];
    float r = rsqrtf(tot * (1.0f / (float)DIM_) + EPS_);
    const float4* wr = (const float4*)w;
    float4 wa = wr[t], wb = wr[t + 256];
    float va[4] = {a.x*r*wa.x, a.y*r*wa.y, a.z*r*wa.z, a.w*r*wa.w};
    float vb[4] = {b.x*r*wb.x, b.y*r*wb.y, b.z*r*wb.z, b.w*r*wb.w};
    __nv_bfloat16 h0, h1, h2, h3, l0, l1, l2, l3;
    size_t base = (size_t)row * DIM_;
    bsplit(va[0], h0, l0); bsplit(va[1], h1, l1);
    bsplit(va[2], h2, l2); bsplit(va[3], h3, l3);
    ((__nv_bfloat162*)(yhi + base + t*4))[0] = __halves2bfloat162(h0, h1);
    ((__nv_bfloat162*)(yhi + base + t*4))[1] = __halves2bfloat162(h2, h3);
    ((__nv_bfloat162*)(ylo + base + t*4))[0] = __halves2bfloat162(l0, l1);
    ((__nv_bfloat162*)(ylo + base + t*4))[1] = __halves2bfloat162(l2, l3);
    bsplit(vb[0], h0, l0); bsplit(vb[1], h1, l1);
    bsplit(vb[2], h2, l2); bsplit(vb[3], h3, l3);
    ((__nv_bfloat162*)(yhi + base + (t+256)*4))[0] = __halves2bfloat162(h0, h1);
    ((__nv_bfloat162*)(yhi + base + (t+256)*4))[1] = __halves2bfloat162(h2, h3);
    ((__nv_bfloat162*)(ylo + base + (t+256)*4))[0] = __halves2bfloat162(l0, l1);
    ((__nv_bfloat162*)(ylo + base + (t+256)*4))[1] = __halves2bfloat162(l2, l3);
}

__global__ void qkv_concat_k(const float* __restrict__ wq, const float* __restrict__ wk,
                             const float* __restrict__ wv, float* __restrict__ out) {
    size_t idx = (size_t)blockIdx.x * blockDim.x + threadIdx.x;
    size_t n4 = idx % 768, kk = idx / 768;
    size_t n = n4 * 4;
    float4 v;
    if (n < 2048)      v = *(const float4*)(wq + kk * 2048 + n);
    else if (n < 2560) v = *(const float4*)(wk + kk * 512 + (n - 2048));
    else               v = *(const float4*)(wv + kk * 512 + (n - 2560));
    ((float4*)out)[idx] = v;
}

__global__ void rope_pk(float* __restrict__ base, int nheads, int col_off) {
    int idx = blockIdx.x * blockDim.x + threadIdx.x;
    int i    = idx & 63;
    int rest = idx >> 6;
    int h    = rest % nheads;
    int row  = rest / nheads;
    int l    = row & (L_ - 1);
    double e   = -(double)(2 * i) * (1.0 / (double)HD_) * 9.210340371976184;
    double ang = (double)l * exp(e);
    double sd, cd;
    sincos(ang, &sd, &cd);
    float c = (float)cd, s = (float)sd;
    float2* p = (float2*)(base + (size_t)row * 3072 + col_off + h * HD_) + i;
    float2 xv = *p;
    *p = make_float2(xv.x * c - xv.y * s, xv.x * s + xv.y * c);
}

// smem-tiled sliding-window GQA attention (round 16 verbatim)
#define CK 64
#define ASMEM (2 * CK * HD_ * 4)

__global__ __launch_bounds__(1024)
void attn_tile_k(const float* __restrict__ qkv,
                 __nv_bfloat16* __restrict__ ohi, __nv_bfloat16* __restrict__ olo) {
    extern __shared__ float sbuf[];
    float* sk = sbuf;
    float* sv = sbuf + CK * HD_;

    const int w    = threadIdx.x >> 5;
    const int lane = threadIdx.x & 31;
    const int q0   = blockIdx.x * 8;
    const int kvh  = blockIdx.y;
    const int b    = blockIdx.z;
    const int qpos = q0 + (w >> 2);
    const int h    = kvh * 4 + (w & 3);

    const float4* qp = (const float4*)(qkv + (size_t)(b * L_ + qpos) * 3072 + h * HD_);
    const float4  qv = qp[lane];

    int start = qpos - (WIN_ - 1); if (start < 0) start = 0;
    int start0 = q0 - (WIN_ - 1);  if (start0 < 0) start0 = 0;
    const int base0 = start0 & ~(CK - 1);
    const int qend  = q0 + 7;
    const float SCALE = 11.313708498984761f;

    float m = -1e30f, ssum = 0.f;
    float4 acc = make_float4(0.f, 0.f, 0.f, 0.f);

    for (int base = base0; base <= qend; base += CK) {
        __syncthreads();
        for (int i = threadIdx.x; i < CK * 32; i += 1024) {
            int row = i >> 5, c4 = i & 31;
            size_t g = ((size_t)(b * L_ + base + row)) * 3072 + 2048 + kvh * HD_ + c4 * 4;
            ((float4*)sk)[i] = *(const float4*)(qkv + g);
            ((float4*)sv)[i] = *(const float4*)(qkv + g + 512);
        }
        __syncthreads();

        int lo = start > base ? start : base;
        int hi = qpos < base + CK - 1 ? qpos : base + CK - 1;
        for (int kp = lo; kp <= hi; ++kp) {
            float4 kv4 = ((const float4*)sk)[(kp - base) * 32 + lane];
            float d = qv.x*kv4.x + qv.y*kv4.y + qv.z*kv4.z + qv.w*kv4.w;
            d += __shfl_xor_sync(0xffffffffu, d, 16);
            d += __shfl_xor_sync(0xffffffffu, d, 8);
            d += __shfl_xor_sync(0xffffffffu, d, 4);
            d += __shfl_xor_sync(0xffffffffu, d, 2);
            d += __shfl_xor_sync(0xffffffffu, d, 1);
            float sc   = d * SCALE;
            float nm   = fmaxf(m, sc);
            float emax = __expf(-fabsf(sc - m));
            bool  up   = sc > m;
            float corr = up ? emax : 1.0f;
            float p    = up ? 1.0f : emax;
            float4 vv  = ((const float4*)sv)[(kp - base) * 32 + lane];
            ssum  = ssum * corr + p;
            acc.x = acc.x * corr + p * vv.x;
            acc.y = acc.y * corr + p * vv.y;
            acc.z = acc.z * corr + p * vv.z;
            acc.w = acc.w * corr + p * vv.w;
            m = nm;
        }
    }

    float inv = 1.f / ssum;
    float o0 = acc.x * inv, o1 = acc.y * inv, o2 = acc.z * inv, o3 = acc.w * inv;
    __nv_bfloat16 h0, h1, h2, h3, l0, l1, l2, l3;
    bsplit(o0, h0, l0); bsplit(o1, h1, l1); bsplit(o2, h2, l2); bsplit(o3, h3, l3);
    size_t obase = ((size_t)(b * L_ + qpos) * NH_ + h) * HD_ + lane * 4;
    ((__nv_bfloat162*)(ohi + obase))[0] = __halves2bfloat162(h0, h1);
    ((__nv_bfloat162*)(ohi + obase))[1] = __halves2bfloat162(h2, h3);
    ((__nv_bfloat162*)(olo + obase))[0] = __halves2bfloat162(l0, l1);
    ((__nv_bfloat162*)(olo + obase))[1] = __halves2bfloat162(l2, l3);
}

// ---------------- f32x2 packed-FMA SGEMM — 128x64 tile, 3 CTAs/SM ----------------
// Per-element FMA chain unchanged (ascending k): bit-identical to prior rounds.
#define BM 128
#define BN 64
#define BK 8

__device__ __forceinline__ uint64_t packdup(float x) {
    uint64_t u;
    uint32_t b = __float_as_uint(x);
    asm("mov.b64 %0, {%1, %2};" : "=l"(u) : "r"(b), "r"(b));
    return u;
}
__device__ __forceinline__ void unpack2(uint64_t u, float& lo, float& hi) {
    uint32_t a, b;
    asm("mov.b64 {%0, %1}, %2;" : "=r"(a), "=r"(b) : "l"(u));
    lo = __uint_as_float(a);
    hi = __uint_as_float(b);
}

__global__ __launch_bounds__(256, 3)
void sgemm_k(const float* __restrict__ A, const float* __restrict__ B,
             float* __restrict__ C, int M, int N, int K) {
    __shared__ float As[2][BK][BM];
    __shared__ float Bs[2][BK][BN];

    const int tid = threadIdx.x;
    const int tc  = tid & 15;          // 16 cols x 4 floats = 64
    const int tr  = tid >> 4;          // 16 rows x 8 floats = 128

    const int num_m = M >> 7, num_n = N >> 6;
    int pid   = blockIdx.x;
    int width = 8 * num_n;
    int gid   = pid / width;
    int rem   = num_m - gid * 8;
    int gsz   = rem < 8 ? rem : 8;
    int pm    = gid * 8 + (pid % gsz);
    int pn    = (pid % width) / gsz;
    const int row0 = pm << 7, col0 = pn << 6;

    const int a_r = tid >> 1;
    const int a_c = (tid & 1) << 2;
    const int b_r = tid >> 4;          // threads 0..127 load B (8 x 64)
    const int b_c = (tid & 15) << 2;

    const float* Ap = A + (size_t)(row0 + a_r) * K + a_c;
    const float* Bp = B + (size_t)b_r * N + col0 + b_c;

    uint64_t acc2[4][4];
#pragma unroll
    for (int i = 0; i < 4; ++i)
#pragma unroll
        for (int j = 0; j < 4; ++j) acc2[i][j] = 0ull;

    float4 av = *(const float4*)Ap;  Ap += BK;
    float4 bv;
    if (tid < 128) { bv = *(const float4*)Bp;  Bp += (size_t)BK * N; }
    As[0][a_c + 0][a_r] = av.x;
    As[0][a_c + 1][a_r] = av.y;
    As[0][a_c + 2][a_r] = av.z;
    As[0][a_c + 3][a_r] = av.w;
    if (tid < 128) *(float4*)&Bs[0][b_r][b_c] = bv;
    __syncthreads();

    const int CH = K / BK;
    for (int c = 0; c < CH; ++c) {
        const int buf = c & 1;
        if (c + 1 < CH) {
            av = *(const float4*)Ap;  Ap += BK;
            if (tid < 128) { bv = *(const float4*)Bp;  Bp += (size_t)BK * N; }
        }
#pragma unroll
        for (int kk = 0; kk < BK; ++kk) {
            const uint64_t* ap2 = (const uint64_t*)&As[buf][kk][tr * 8];
            uint64_t a2_0 = ap2[0], a2_1 = ap2[1], a2_2 = ap2[2], a2_3 = ap2[3];
            float br[4];
            *(float4*)&br[0] = *(const float4*)&Bs[buf][kk][tc * 4];
#pragma unroll
            for (int j = 0; j < 4; ++j) {
                uint64_t b2 = packdup(br[j]);
                asm("fma.rn.f32x2 %0, %1, %2, %0;" : "+l"(acc2[0][j]) : "l"(a2_0), "l"(b2));
                asm("fma.rn.f32x2 %0, %1, %2, %0;" : "+l"(acc2[1][j]) : "l"(a2_1), "l"(b2));
                asm("fma.rn.f32x2 %0, %1, %2, %0;" : "+l"(acc2[2][j]) : "l"(a2_2), "l"(b2));
                asm("fma.rn.f32x2 %0, %1, %2, %0;" : "+l"(acc2[3][j]) : "l"(a2_3), "l"(b2));
            }
        }
        if (c + 1 < CH) {
            const int nb = buf ^ 1;
            As[nb][a_c + 0][a_r] = av.x;
            As[nb][a_c + 1][a_r] = av.y;
            As[nb][a_c + 2][a_r] = av.z;
            As[nb][a_c + 3][a_r] = av.w;
            if (tid < 128) *(float4*)&Bs[nb][b_r][b_c] = bv;
        }
        __syncthreads();
    }

#pragma unroll
    for (int i2 = 0; i2 < 4; ++i2) {
        float lo[4], hi[4];
#pragma unroll
        for (int j = 0; j < 4; ++j) unpack2(acc2[i2][j], lo[j], hi[j]);
        size_t r_lo = (size_t)(row0 + tr * 8 + 2 * i2);
        size_t r_hi = r_lo + 1;
        *(float4*)(C + r_lo * N + col0 + tc * 4) = make_float4(lo[0], lo[1], lo[2], lo[3]);
        *(float4*)(C + r_hi * N + col0 + tc * 4) = make_float4(hi[0], hi[1], hi[2], hi[3]);
    }
}

static inline void sgemm(const float* A, const float* B, float* C,
                         int M, int N, int K, cudaStream_t st) {
    int tiles = (M / BM) * (N / BN);
    sgemm_k<<<tiles, 256, 0, st>>>(A, B, C, M, N, K);
}

// ======================================================================
// PART 2: bf16 hi/lo 3-term mma GEMM (round 16 verbatim)
// ======================================================================

__device__ __forceinline__ void cp16(uint32_t s, const void* g) {
    asm volatile("cp.async.cg.shared.global [%0], [%1], 16;" :: "r"(s), "l"(g));
}
__device__ __forceinline__ void ldsm4(uint32_t* r, uint32_t addr) {
    asm volatile("ldmatrix.sync.aligned.m8n8.x4.shared.b16 {%0,%1,%2,%3}, [%4];"
                 : "=r"(r[0]), "=r"(r[1]), "=r"(r[2]), "=r"(r[3]) : "r"(addr));
}
#define MMA16816(d, a, b) \
    asm volatile("mma.sync.aligned.m16n8k16.row.col.f32.bf16.bf16.f32 " \
        "{%0,%1,%2,%3}, {%4,%5,%6,%7}, {%8,%9}, {%0,%1,%2,%3};" \
        : "+f"((d)[0]), "+f"((d)[1]), "+f"((d)[2]), "+f"((d)[3]) \
        : "r"((a)[0]), "r"((a)[1]), "r"((a)[2]), "r"((a)[3]), "r"((b)[0]), "r"((b)[1]))

__device__ __forceinline__ uint32_t swz(int row, int ck) {
    return (uint32_t)((row * 4 + (ck ^ ((row >> 1) & 3))) * 16);
}

#define MSTG_BYTES 32768
#define MGSMEM (3 * MSTG_BYTES)

__global__ __launch_bounds__(128, 2)
void mma_gemm_k(const __nv_bfloat16* __restrict__ Ahi, const __nv_bfloat16* __restrict__ Alo,
                const __nv_bfloat16* __restrict__ Bhi, const __nv_bfloat16* __restrict__ Blo,
                const float* __restrict__ R, float* __restrict__ C,
                __nv_bfloat16* __restrict__ Ghi, __nv_bfloat16* __restrict__ Glo,
                int M, int N, int K, int EPI) {
    extern __shared__ __align__(128) char smem[];
    const uint32_t sb = smem_u32(smem);
    const int tid = threadIdx.x, wid = tid >> 5, lane = tid & 31;

    const int num_n = N >> 7;
    int pid = blockIdx.x;
    const int GM = 8;
    int width = GM * num_n;
    int gid = pid / width;
    int rem = (M >> 7) - gid * GM;
    int gsz = rem < GM ? rem : GM;
    int pm = gid * GM + (pid % gsz);
    int pn = (pid % width) / gsz;
    const int m0 = pm << 7, n0 = pn << 7;

    const size_t Kb = (size_t)K * 2;
    const int CH = K >> 5;

    const int wm = (wid >> 1) * 64;
    const int wn = (wid & 1) * 64;

    float acc[4][8][4];
#pragma unroll
    for (int i = 0; i < 4; ++i)
#pragma unroll
        for (int j = 0; j < 8; ++j)
#pragma unroll
            for (int r = 0; r < 4; ++r) acc[i][j][r] = 0.f;

    auto load = [&](int s, int chunk) {
        uint32_t st = sb + (uint32_t)s * (uint32_t)MSTG_BYTES;
        size_t kb0 = (size_t)chunk * 64;
#pragma unroll
        for (int part = 0; part < 4; ++part) {
            int q = part * 128 + tid;
            int r = q >> 2, ck = q & 3;
            uint32_t so = swz(r, ck);
            size_t ga = (size_t)(m0 + r) * Kb + kb0 + (size_t)ck * 16;
            size_t gb = (size_t)(n0 + r) * Kb + kb0 + (size_t)ck * 16;
            cp16(st +          so, (const char*)Ahi + ga);
            cp16(st +  8192u + so, (const char*)Alo + ga);
            cp16(st + 16384u + so, (const char*)Bhi + gb);
            cp16(st + 24576u + so, (const char*)Blo + gb);
        }
    };

    load(0, 0);
    asm volatile("cp.async.commit_group;" ::: "memory");
    load(1, 1);
    asm volatile("cp.async.commit_group;" ::: "memory");

    const int a_row = wm + (lane & 7) + ((lane >> 3) & 1) * 8;
    const int a_ckl = (lane >> 4) & 1;
    const int b_row = wn + (lane & 7) + ((lane >> 4) & 1) * 8;
    const int b_ckl = (lane >> 3) & 1;

    for (int c = 0; c < CH; ++c) {
        const int s = c % 3;
        if (c + 1 < CH) asm volatile("cp.async.wait_group 1;" ::: "memory");
        else            asm volatile("cp.async.wait_group 0;" ::: "memory");
        __syncthreads();
        if (c + 2 < CH) {
            load((c + 2) % 3, c + 2);
            asm volatile("cp.async.commit_group;" ::: "memory");
        }
        const uint32_t stA  = sb + (uint32_t)s * (uint32_t)MSTG_BYTES;
        const uint32_t stAl = stA + 8192u;
        const uint32_t stB  = stA + 16384u;
        const uint32_t stBl = stA + 24576u;
#pragma unroll
        for (int ks = 0; ks < 2; ++ks) {
            const int cka = ks * 2 + a_ckl;
            const int ckb = ks * 2 + b_ckl;
            uint32_t Ah[4][4], Al[4][4];
#pragma unroll
            for (int mi = 0; mi < 4; ++mi) {
                uint32_t so = swz(a_row + mi * 16, cka);
                ldsm4(Ah[mi], stA  + so);
                ldsm4(Al[mi], stAl + so);
            }
#pragma unroll
            for (int nq = 0; nq < 4; ++nq) {
                uint32_t Bh[4], Bl[4];
                uint32_t so = swz(b_row + nq * 16, ckb);
                ldsm4(Bh, stB  + so);
                ldsm4(Bl, stBl + so);
#pragma unroll
                for (int mi = 0; mi < 4; ++mi)
#pragma unroll
                    for (int jj = 0; jj < 2; ++jj) {
                        const int nj = nq * 2 + jj;
                        MMA16816(acc[mi][nj], Ah[mi], &Bh[jj * 2]);
                        MMA16816(acc[mi][nj], Al[mi], &Bh[jj * 2]);
                        MMA16816(acc[mi][nj], Ah[mi], &Bl[jj * 2]);
                    }
            }
        }
    }

#pragma unroll
    for (int mi = 0; mi < 4; ++mi) {
        int r0 = m0 + wm + mi * 16 + (lane >> 2);
#pragma unroll
        for (int nj = 0; nj < 8; ++nj) {
            int c0 = n0 + wn + nj * 8 + (lane & 3) * 2;
            if (EPI == 2) {
                int j0 = c0 >> 1;
                float gA = acc[mi][nj][0] / (1.f + __expf(-acc[mi][nj][0])) * acc[mi][nj][1];
                float gB = acc[mi][nj][2] / (1.f + __expf(-acc[mi][nj][2])) * acc[mi][nj][3];
                __nv_bfloat16 hh, ll;
                bsplit(gA, hh, ll);
                Ghi[(size_t)r0 * FF_ + j0] = hh;
                Glo[(size_t)r0 * FF_ + j0] = ll;
                bsplit(gB, hh, ll);
                Ghi[(size_t)(r0 + 8) * FF_ + j0] = hh;
                Glo[(size_t)(r0 + 8) * FF_ + j0] = ll;
            } else {
                float2 v0 = make_float2(acc[mi][nj][0], acc[mi][nj][1]);
                float2 v1 = make_float2(acc[mi][nj][2], acc[mi][nj][3]);
                if (EPI == 1) {
                    float2 q0 = *(const float2*)(R + (size_t)r0 * N + c0);
                    float2 q1 = *(const float2*)(R + (size_t)(r0 + 8) * N + c0);
                    v0.x += q0.x; v0.y += q0.y;
                    v1.x += q1.x; v1.y += q1.y;
                }
                *(float2*)(C + (size_t)r0 * N + c0)       = v0;
                *(float2*)(C + (size_t)(r0 + 8) * N + c0) = v1;
            }
        }
    }
}

__global__ __launch_bounds__(256) void cvt_wT_k(const float* __restrict__ W,
        __nv_bfloat16* __restrict__ hiT, __nv_bfloat16* __restrict__ loT,
        int K, int N, int cstride, int coff) {
    __shared__ float t[32][33];
    int tx = threadIdx.x, ty = threadIdx.y;
    int nb = blockIdx.x * 32, kb = blockIdx.y * 32;
#pragma unroll
    for (int r = 0; r < 4; ++r)
        t[ty + 8 * r][tx] = W[(size_t)(kb + ty + 8 * r) * N + nb + tx];
    __syncthreads();
#pragma unroll
    for (int r = 0; r < 4; ++r) {
        float v = t[tx][ty + 8 * r];
        __nv_bfloat16 h = __float2bfloat16_rn(v);
        __nv_bfloat16 l = __float2bfloat16_rn(v - __bfloat162float(h));
        size_t o = ((size_t)(nb + ty + 8 * r) * cstride + coff) * K + kb + tx;
        hiT[o] = h; loT[o] = l;
    }
}

static void bmma(const __nv_bfloat16* ahi, const __nv_bfloat16* alo,
                 const __nv_bfloat16* bhi, const __nv_bfloat16* blo,
                 const float* R, float* C,
                 __nv_bfloat16* ghi, __nv_bfloat16* glo,
                 int M, int N, int K, int epi) {
    int tiles = (M / 128) * (N / 128);
    mma_gemm_k<<<tiles, 128, MGSMEM>>>(ahi, alo, bhi, blo, R, C, ghi, glo, M, N, K, epi);
}

static void cvt_w(const float* W, __nv_bfloat16* hiT, __nv_bfloat16* loT,
                  int K, int N, int cstride, int coff, cudaStream_t st) {
    dim3 g(N / 32, K / 32), b(32, 8);
    cvt_wT_k<<<g, b, 0, st>>>(W, hiT, loT, K, N, cstride, coff);
}

// ================= launch =================
extern "C" void kernel_launch(void* const* d_in, const int* in_sizes, int n_in,
                              void* d_out, int out_size) {
    const int*   ids = (const int*)  d_in[0];
    const float* tok = (const float*)d_in[1];
    const float* anw = (const float*)d_in[2];
    const float* wq  = (const float*)d_in[3];
    const float* wk  = (const float*)d_in[4];
    const float* wv  = (const float*)d_in[5];
    const float* wo  = (const float*)d_in[6];
    const float* fnw = (const float*)d_in[7];
    const float* w1  = (const float*)d_in[8];
    const float* w2  = (const float*)d_in[9];
    const float* w3  = (const float*)d_in[10];
    const float* nw  = (const float*)d_in[11];
    const float* ow  = (const float*)d_in[12];
    float* out = (float*)d_out;

    cudaFuncSetAttribute(mma_gemm_k,  cudaFuncAttributeMaxDynamicSharedMemorySize, MGSMEM);
    cudaFuncSetAttribute(attn_tile_k, cudaFuncAttributeMaxDynamicSharedMemorySize, ASMEM);

    float *h, *x, *qkv, *wqkv;
    __nv_bfloat16 *ahi, *alo, *bhi, *blo, *whi, *wlo;
    cudaGetSymbolAddress((void**)&h,    g_h);
    cudaGetSymbolAddress((void**)&x,    g_x);
    cudaGetSymbolAddress((void**)&qkv,  g_qkv);
    cudaGetSymbolAddress((void**)&wqkv, g_wqkv);
    cudaGetSymbolAddress((void**)&ahi,  g_ahi);
    cudaGetSymbolAddress((void**)&alo,  g_alo);
    cudaGetSymbolAddress((void**)&bhi,  g_bhi);
    cudaGetSymbolAddress((void**)&blo,  g_blo);
    cudaGetSymbolAddress((void**)&whi,  g_whi);
    cudaGetSymbolAddress((void**)&wlo,  g_wlo);

    // second stream for weight preprocessing (fork/join via events; capture-legal)
    cudaStream_t s2;
    cudaEvent_t evF, evJ;
    cudaStreamCreateWithFlags(&s2, cudaStreamNonBlocking);
    cudaEventCreateWithFlags(&evF, cudaEventDisableTiming);
    cudaEventCreateWithFlags(&evJ, cudaEventDisableTiming);

    cudaEventRecord(evF, 0);
    cudaStreamWaitEvent(s2, evF, 0);

    // ---- s2: weight bf16 planes + L1 qkv concat (all independent of h) ----
    for (int l = 0; l < 2; ++l) {
        cvt_w(wo + (size_t)l*2048ull*DIM_, whi + WOB(l),  wlo + WOB(l),  2048, DIM_, 1, 0, s2);
        cvt_w(w1 + (size_t)l*DIM_*FF_,     whi + W13B(l), wlo + W13B(l), DIM_, FF_, 2, 0, s2);
        cvt_w(w3 + (size_t)l*DIM_*FF_,     whi + W13B(l), wlo + W13B(l), DIM_, FF_, 2, 1, s2);
        cvt_w(w2 + (size_t)l*FF_*DIM_,     whi + W2B(l),  wlo + W2B(l),  FF_, DIM_, 1, 0, s2);
    }
    cvt_w(ow, whi + OWB, wlo + OWB, DIM_, V_, 1, 0, s2);
    qkv_concat_k<<<(DIM_ * 768) / 256, 256, 0, s2>>>(
        wq + (size_t)DIM_ * 2048, wk + (size_t)DIM_ * 512,
        wv + (size_t)DIM_ * 512,  wqkv + (size_t)DIM_ * 3072);
    cudaEventRecord(evJ, s2);

    // ---- main stream: L0 front (overlaps with s2) ----
    qkv_concat_k<<<(DIM_ * 768) / 256, 256>>>(wq, wk, wv, wqkv);
    embed_k<<<NTOK, 256>>>(ids, tok, h);

    bool joined = false;
    for (int l = 0; l < 2; ++l) {
        rmsnorm_k<<<NTOK, 256>>>(h, anw + (size_t)l * DIM_, x);
        sgemm(x, wqkv + (size_t)l * DIM_ * 3072, qkv, NTOK, 3072, DIM_, 0);
        rope_pk<<<(NTOK * NH_  * 64) / 256, 256>>>(qkv, NH_, 0);
        rope_pk<<<(NTOK * NKV_ * 64) / 256, 256>>>(qkv, NKV_, 2048);

        dim3 ag(L_ / 8, NKV_, B_);
        attn_tile_k<<<ag, 1024, ASMEM>>>(qkv, ahi, alo);

        if (!joined) { cudaStreamWaitEvent(0, evJ, 0); joined = true; }

        bmma(ahi, alo, whi + WOB(l), wlo + WOB(l), h, h, nullptr, nullptr,
             NTOK, DIM_, 2048, 1);

        rmsnorm_cvt_k<<<NTOK, 256>>>(h, fnw + (size_t)l * DIM_, ahi, alo);
        bmma(ahi, alo, whi + W13B(l), wlo + W13B(l), nullptr, nullptr, bhi, blo,
             NTOK, 16384, DIM_, 2);

        bmma(bhi, blo, whi + W2B(l), wlo + W2B(l), h, h, nullptr, nullptr,
             NTOK, DIM_, FF_, 1);
    }

    rmsnorm_cvt_k<<<NTOK, 256>>>(h, nw, ahi, alo);
    bmma(ahi, alo, whi + OWB, wlo + OWB, nullptr, out, nullptr, nullptr,
         NTOK, V_, DIM_, 0);
}